// round 7
// baseline (speedup 1.0000x reference)
#include <cuda_runtime.h>
#include <cuda_bf16.h>

#define NG 1024
#define DG 128
#define HG 256
#define JCH 8            // j-split factor
#define JW (NG / JCH)    // 128 j per chunk

typedef unsigned long long u64;

// ---- scratch (no allocations allowed) ----
__device__ float g_src[NG * HG];            // X @ W1a^T + b1
__device__ float g_nbr[NG * HG];            // X @ W1b^T
__device__ float g_part[JCH][NG * HG];      // per-j-chunk partials (8MB)
__device__ float g_degp[JCH][NG];           // per-chunk degree partials
__device__ float g_agg[NG * HG];            // folded aggregation
__device__ float g_deg[NG];
__device__ float g_combo[384 * HG];         // W_ih @ W2   [384,256]
__device__ float g_bvec[384];               // W_ih @ b2
__device__ float g_gi[NG * 3 * DG];
__device__ float g_gh[NG * 3 * DG];
__device__ int   g_cnt[NG / 8];             // fold arrival counters (zero-init, self-resetting)

// ---- packed f32x2 helpers (Blackwell) ----
__device__ __forceinline__ u64 pk2(float lo, float hi) {
    u64 r; asm("mov.b64 %0, {%1, %2};" : "=l"(r) : "f"(lo), "f"(hi)); return r;
}
__device__ __forceinline__ float2 upk(u64 v) {
    float2 r; asm("mov.b64 {%0, %1}, %2;" : "=f"(r.x), "=f"(r.y) : "l"(v)); return r;
}
__device__ __forceinline__ u64 add2(u64 a, u64 b) {
    u64 r; asm("add.rn.f32x2 %0, %1, %2;" : "=l"(r) : "l"(a), "l"(b)); return r;
}
__device__ __forceinline__ void fma2(u64& acc, u64 a, u64 b) {
    asm("fma.rn.f32x2 %0, %1, %2, %0;" : "+l"(acc) : "l"(a), "l"(b));
}

// ============================================================
// PREP launch: src | nbr | gh | combo | bvec  (everything that only needs
// X + weights). B-resident GEMM: weight slab staged to smem ONCE (one sync),
// A streamed from L2 via broadcast LDGs. K=128, BN=64, M-chunk=32.
// grid: x = role (0-3 src, 4-7 nbr, 8-13 gh, 14-17 combo, 18 bvec), y = M-chunk.
// ============================================================
__global__ __launch_bounds__(256, 4) void prep_kernel(
    const float* __restrict__ X,
    const float* __restrict__ W1,
    const float* __restrict__ b1,
    const float* __restrict__ W_hh,
    const float* __restrict__ b_hh,
    const float* __restrict__ W_ih,
    const float* __restrict__ W2,
    const float* __restrict__ b2)
{
    __shared__ float Bs[128][64];             // 32KB
    const int bx = blockIdx.x;
    const int by = blockIdx.y;
    const int tid = threadIdx.x;

    if (bx == 18) {                           // ---- bvec = W_ih @ b2 ----
        if (by != 0) return;
        __shared__ float b2s[DG];
        if (tid < DG) b2s[tid] = b2[tid];
        __syncthreads();
        for (int g = tid; g < 384; g += 256) {
            const float* w = W_ih + (size_t)g * DG;
            float a0 = 0.f, a1 = 0.f, a2 = 0.f, a3 = 0.f;
#pragma unroll
            for (int d = 0; d < DG; d += 4) {
                a0 = fmaf(w[d],     b2s[d],     a0);
                a1 = fmaf(w[d + 1], b2s[d + 1], a1);
                a2 = fmaf(w[d + 2], b2s[d + 2], a2);
                a3 = fmaf(w[d + 3], b2s[d + 3], a3);
            }
            g_bvec[g] = (a0 + a1) + (a2 + a3);
        }
        return;
    }

    // ---- role selection ----
    const float* A = X; int lda = DG;
    const float* Brow = nullptr; int ldb = 0;
    const float* Bcm = nullptr;               // col-contiguous B (combo role)
    const float* bias = nullptr;
    float* C; int ldc; int col0; const int row0 = by * 32;

    if (bx < 4)       { Brow = W1;       ldb = 2 * DG; bias = b1;   C = g_src;   ldc = HG;  col0 = bx * 64; }
    else if (bx < 8)  { Brow = W1 + DG;  ldb = 2 * DG;              C = g_nbr;   ldc = HG;  col0 = (bx - 4) * 64; }
    else if (bx < 14) { Brow = W_hh;     ldb = DG;     bias = b_hh; C = g_gh;    ldc = 384; col0 = (bx - 8) * 64; }
    else              { if (by >= 12) return;
                        A = W_ih; Bcm = W2; ldb = HG;  C = g_combo; ldc = HG;  col0 = (bx - 14) * 64; }

    // ---- stage Bs[k][c] (once) ----
    if (Brow) {      // B row-major [N,K]: Bs[k][c] = Brow[(col0+c)*ldb + k]
        int c = tid >> 2;                    // 0..63
        int j = (tid & 3) * 4;               // k-offset 0,4,8,12
        const float* bp = Brow + (size_t)(col0 + c) * ldb;
#pragma unroll
        for (int kq = 0; kq < 128; kq += 16) {
            float4 v = *(const float4*)(bp + kq + j);
            Bs[kq + j + 0][c] = v.x; Bs[kq + j + 1][c] = v.y;
            Bs[kq + j + 2][c] = v.z; Bs[kq + j + 3][c] = v.w;
        }
    } else {         // B col-contiguous: Bs[k][c] = Bcm[k*ldb + col0 + c]
#pragma unroll
        for (int it = 0; it < 8; ++it) {
            int idx = tid + it * 256;        // 0..2047
            int k = idx >> 4;
            int c4 = (idx & 15) * 4;
            *(float4*)&Bs[k][c4] = *(const float4*)(Bcm + (size_t)k * ldb + col0 + c4);
        }
    }
    __syncthreads();

    // ---- compute: 2 rows x 4 cols per thread ----
    const int tc = tid & 15;
    const int tr = tid >> 4;
    const float* a0p = A + (size_t)(row0 + tr * 2) * lda;
    const float* a1p = a0p + lda;

    u64 acc00 = 0ull, acc01 = 0ull, acc10 = 0ull, acc11 = 0ull;
#pragma unroll 8
    for (int k0 = 0; k0 < 128; k0 += 4) {
        float4 a0 = *(const float4*)(a0p + k0);
        float4 a1 = *(const float4*)(a1p + k0);
#pragma unroll
        for (int kk = 0; kk < 4; ++kk) {
            float4 b = *(const float4*)&Bs[k0 + kk][tc * 4];
            u64 b01 = pk2(b.x, b.y);
            u64 b23 = pk2(b.z, b.w);
            float av0 = (&a0.x)[kk], av1 = (&a1.x)[kk];
            u64 A0 = pk2(av0, av0);
            u64 A1 = pk2(av1, av1);
            fma2(acc00, A0, b01); fma2(acc01, A0, b23);
            fma2(acc10, A1, b01); fma2(acc11, A1, b23);
        }
    }

    u64 accs[2][2] = {{acc00, acc01}, {acc10, acc11}};
#pragma unroll
    for (int r = 0; r < 2; ++r) {
        int row = row0 + tr * 2 + r;
#pragma unroll
        for (int cp = 0; cp < 2; ++cp) {
            float2 f = upk(accs[r][cp]);
            int col = col0 + tc * 4 + cp * 2;
            if (bias) { f.x += bias[col]; f.y += bias[col + 1]; }
            C[(size_t)row * ldc + col]     = f.x;
            C[(size_t)row * ldc + col + 1] = f.y;
        }
    }
}

// ============================================================
// part[jb][i,h] = sum_{j in chunk jb} mask[i,j]*relu(src[i,h]+nbr[j,h])
// (exact R4-proven inner loop). Last-arriving CTA per i-block folds the
// 8 partials into g_agg and g_deg (fixed c-order -> bit-deterministic).
// ============================================================
__global__ __launch_bounds__(256, 5) void agg_part_kernel(const int* __restrict__ adj)
{
    __shared__ __align__(16) float msh[JW][8];
    const int i0 = blockIdx.x * 8;
    const int jb = blockIdx.y;
    const int j0 = jb * JW;
    const int tid = threadIdx.x;

#pragma unroll
    for (int it = 0; it < 4; ++it) {
        int idx = tid + it * 256;          // 0..1023
        int t = idx >> 7;                  // 0..7
        int j = idx & 127;
        msh[j][t] = (adj[(size_t)(i0 + t) * NG + j0 + j] > 0) ? 1.f : 0.f;
    }
    __syncthreads();

    // degree partials: warp w handles row t=w
    {
        int w = tid >> 5, lane = tid & 31;
        float ds = 0.f;
#pragma unroll
        for (int k = 0; k < 4; ++k) ds += msh[lane + 32 * k][w];
#pragma unroll
        for (int off = 16; off > 0; off >>= 1)
            ds += __shfl_down_sync(0xFFFFFFFFu, ds, off);
        if (lane == 0) g_degp[jb][i0 + w] = ds;
    }

    const int h = tid;
    u64 s2[4], acc2[4];
#pragma unroll
    for (int p = 0; p < 4; ++p) {
        s2[p] = pk2(g_src[(size_t)(i0 + 2 * p) * HG + h],
                    g_src[(size_t)(i0 + 2 * p + 1) * HG + h]);
        acc2[p] = 0ull;
    }
    const float* nb = g_nbr + (size_t)j0 * HG + h;

#pragma unroll 4
    for (int j = 0; j < JW; ++j) {
        float nv = __ldg(nb + (size_t)j * HG);
        u64 nv2 = pk2(nv, nv);
        ulonglong2 ma = *(const ulonglong2*)&msh[j][0];
        ulonglong2 mb = *(const ulonglong2*)&msh[j][4];
        {
            u64 t = add2(s2[0], nv2); float2 f = upk(t);
            f.x = fmaxf(f.x, 0.f); f.y = fmaxf(f.y, 0.f);
            fma2(acc2[0], ma.x, pk2(f.x, f.y));
        }
        {
            u64 t = add2(s2[1], nv2); float2 f = upk(t);
            f.x = fmaxf(f.x, 0.f); f.y = fmaxf(f.y, 0.f);
            fma2(acc2[1], ma.y, pk2(f.x, f.y));
        }
        {
            u64 t = add2(s2[2], nv2); float2 f = upk(t);
            f.x = fmaxf(f.x, 0.f); f.y = fmaxf(f.y, 0.f);
            fma2(acc2[2], mb.x, pk2(f.x, f.y));
        }
        {
            u64 t = add2(s2[3], nv2); float2 f = upk(t);
            f.x = fmaxf(f.x, 0.f); f.y = fmaxf(f.y, 0.f);
            fma2(acc2[3], mb.y, pk2(f.x, f.y));
        }
    }

    float* p = g_part[jb];
#pragma unroll
    for (int t = 0; t < 4; ++t) {
        float2 f = upk(acc2[t]);
        p[(size_t)(i0 + 2 * t) * HG + h]     = f.x;
        p[(size_t)(i0 + 2 * t + 1) * HG + h] = f.y;
    }

    // ---- tail-CTA fold ----
    __threadfence();
    __syncthreads();
    __shared__ int is_last;
    if (tid == 0)
        is_last = (atomicAdd(&g_cnt[blockIdx.x], 1) == JCH - 1);
    __syncthreads();
    if (!is_last) return;

#pragma unroll
    for (int it = 0; it < 2; ++it) {
        int idx = tid + it * 256;          // f4 index 0..511 over 8 rows x 256 h
        float4 s = ((const float4*)(g_part[0] + (size_t)i0 * HG))[idx];
#pragma unroll
        for (int c = 1; c < JCH; ++c) {
            float4 v = ((const float4*)(g_part[c] + (size_t)i0 * HG))[idx];
            s.x += v.x; s.y += v.y; s.z += v.z; s.w += v.w;
        }
        ((float4*)(g_agg + (size_t)i0 * HG))[idx] = s;
    }
    if (tid < 8) {
        float d = 0.f;
#pragma unroll
        for (int c = 0; c < JCH; ++c) d += g_degp[c][i0 + tid];
        g_deg[i0 + tid] = d;
    }
    if (tid == 0) g_cnt[blockIdx.x] = 0;   // reset for next graph replay
}

// ============================================================
// gi = agg @ combo^T + deg*bvec + b_ih   (M=1024, N=384, K=256)
// B-resident: combo slab (32 cols x 256 k = 32KB) staged once.
// 256 threads: 1 row x 4 cols each (32 rows x 32 cols per CTA). grid (12,32).
// ============================================================
__global__ __launch_bounds__(256, 4) void gi_kernel(const float* __restrict__ b_ih)
{
    __shared__ float Bs[HG][32];              // 32KB
    const int col0 = blockIdx.x * 32;
    const int row0 = blockIdx.y * 32;
    const int tid = threadIdx.x;

    // stage: Bs[k][c] = combo[(col0+c)*HG + k]
    {
        int c = tid >> 3;                     // 0..31
        int j = (tid & 7) * 4;                // 0..28
        const float* bp = g_combo + (size_t)(col0 + c) * HG;
#pragma unroll
        for (int kq = 0; kq < HG; kq += 32) {
            float4 v = *(const float4*)(bp + kq + j);
            Bs[kq + j + 0][c] = v.x; Bs[kq + j + 1][c] = v.y;
            Bs[kq + j + 2][c] = v.z; Bs[kq + j + 3][c] = v.w;
        }
    }
    __syncthreads();

    const int tc = tid & 7;                   // 4 cols
    const int tr = tid >> 3;                  // 1 row
    const int row = row0 + tr;
    const float* ap = g_agg + (size_t)row * HG;

    u64 acc0 = 0ull, acc1 = 0ull;
#pragma unroll 8
    for (int k0 = 0; k0 < HG; k0 += 4) {
        float4 a = *(const float4*)(ap + k0);
#pragma unroll
        for (int kk = 0; kk < 4; ++kk) {
            float4 b = *(const float4*)&Bs[k0 + kk][tc * 4];
            u64 b01 = pk2(b.x, b.y);
            u64 b23 = pk2(b.z, b.w);
            float av = (&a.x)[kk];
            u64 A0 = pk2(av, av);
            fma2(acc0, A0, b01); fma2(acc1, A0, b23);
        }
    }

    const float d = g_deg[row];
    float2 f0 = upk(acc0), f1 = upk(acc1);
    int col = col0 + tc * 4;
    float* o = g_gi + (size_t)row * 384 + col;
    o[0] = f0.x + fmaf(d, g_bvec[col],     b_ih[col]);
    o[1] = f0.y + fmaf(d, g_bvec[col + 1], b_ih[col + 1]);
    o[2] = f1.x + fmaf(d, g_bvec[col + 2], b_ih[col + 2]);
    o[3] = f1.y + fmaf(d, g_bvec[col + 3], b_ih[col + 3]);
}

// ============================================================
// GRU elementwise:  out = (1-z)*n + z*h
// ============================================================
__global__ __launch_bounds__(256) void gru_kernel(const float* __restrict__ X,
                                                  float* __restrict__ out)
{
    int idx = blockIdx.x * 256 + threadIdx.x;   // 0..131071
    int i = idx >> 7;
    int d = idx & 127;
    const float* gi = g_gi + (size_t)i * 384;
    const float* gh = g_gh + (size_t)i * 384;
    float r = 1.f / (1.f + __expf(-(gi[d] + gh[d])));
    float z = 1.f / (1.f + __expf(-(gi[128 + d] + gh[128 + d])));
    float n = tanhf(gi[256 + d] + r * gh[256 + d]);
    float hprev = X[idx];
    out[idx] = (1.f - z) * n + z * hprev;
}

// ============================================================
extern "C" void kernel_launch(void* const* d_in, const int* in_sizes, int n_in,
                              void* d_out, int out_size)
{
    (void)in_sizes; (void)n_in; (void)out_size;
    const float* X    = (const float*)d_in[0];   // [1024,128]
    const int*   adj  = (const int*)  d_in[1];   // [1024,1024]
    const float* W1   = (const float*)d_in[2];   // [256,256]
    const float* b1   = (const float*)d_in[3];   // [256]
    const float* W2   = (const float*)d_in[4];   // [128,256]
    const float* b2   = (const float*)d_in[5];   // [128]
    const float* W_ih = (const float*)d_in[6];   // [384,128]
    const float* W_hh = (const float*)d_in[7];   // [384,128]
    const float* b_ih = (const float*)d_in[8];   // [384]
    const float* b_hh = (const float*)d_in[9];   // [384]
    float* out = (float*)d_out;

    // 1) everything depending only on X + weights (src|nbr|gh|combo|bvec)
    prep_kernel<<<dim3(19, NG / 32), 256>>>(X, W1, b1, W_hh, b_hh, W_ih, W2, b2);
    // 2) masked relu aggregation + in-kernel tail fold (-> g_agg, g_deg)
    agg_part_kernel<<<dim3(NG / 8, JCH), 256>>>(adj);
    // 3) gi = agg @ combo^T + deg*bvec + b_ih
    gi_kernel<<<dim3(384 / 32, NG / 32), 256>>>(b_ih);
    // 4) GRU gates + output
    gru_kernel<<<(NG * DG) / 256, 256>>>(X, out);
}